// round 12
// baseline (speedup 1.0000x reference)
#include <cuda_runtime.h>

// SNN forward scan: rows = B*N = 65536 independent length-512 recurrences.
// R12: R9 load pipeline (one warp/block, 32 rows, CHUNK=128 -> 512B-run
// coalesced cp.async, double-buffered, 6 warps/SM) + BIT-PACKED output:
// spikes (0/1) are packed into a 2.2KB smem bit buffer during compute and
// the block's entire 64KB output region is written at the end as ONE fully
// contiguous streaming sweep (max-length DRAM write runs; no per-chunk
// store phase inside the pipeline loop).
// Refractory window as multiplicative mask: ic = x*(1-s[t-1])*(1-s[t-2]).

#define T_STEPS 512
#define CHUNK   128
#define ROWS    32                 // threads per block == rows per block
#define NCHUNK  (T_STEPS / CHUNK)  // 4
#define STRIDE  132                // padded smem row stride (floats); conflict-free
#define LDI     32                 // coop cp.async iterations per stage
#define WPC     (CHUNK / 32)       // bit-words per chunk per row = 4
#define WPR     (T_STEPS / 32)     // bit-words per row = 16

__device__ __forceinline__ void cp_async16(float* smem_dst, const float* gmem_src) {
    unsigned saddr = (unsigned)__cvta_generic_to_shared(smem_dst);
    asm volatile("cp.async.cg.shared.global [%0], [%1], 16;\n"
                 :: "r"(saddr), "l"(gmem_src));
}

__global__ __launch_bounds__(ROWS) void snn_fwd_kernel(
    const float* __restrict__ x,
    const float* __restrict__ beta,
    const float* __restrict__ p,
    const float* __restrict__ b,
    float* __restrict__ out,
    int N)
{
    __shared__ float    tile[2][ROWS * STRIDE];
    __shared__ unsigned bits[ROWS][WPR + 1];   // +1 pad -> conflict-free STS

    const int tid = threadIdx.x;
    const size_t row_base = (size_t)blockIdx.x * ROWS;
    const int n = (int)((row_base + tid) % (size_t)N);

    // clamped effective per-neuron params
    const float beta_c = fminf(fmaxf(beta[n], 0.001f), 0.999f);
    const float p_c    = fminf(fabsf(p[n]), 0.999f);
    const float b_c    = fminf(fmaxf(fabsf(b[n]), 0.001f), 1.0f);

    // recurrence state
    float mem = 0.0f, a = 0.0f, vth = 1.0f;
    float m1 = 1.0f, m2 = 1.0f;   // 1 - s(t-1), 1 - s(t-2)

    // ---- load pipeline: preload chunks 0 and 1 (512B-run coalesced) ----
    #pragma unroll
    for (int t = 0; t < 2; ++t) {
        const float* base = x + row_base * T_STEPS + t * CHUNK;
        #pragma unroll
        for (int k = 0; k < LDI; ++k)
            cp_async16(&tile[t][k * STRIDE + tid * 4], base + k * T_STEPS + tid * 4);
        asm volatile("cp.async.commit_group;\n");
    }

    #pragma unroll
    for (int c = 0; c < NCHUNK; ++c) {
        float* buf = tile[c & 1];

        if (c + 1 < NCHUNK) asm volatile("cp.async.wait_group 1;\n");
        else                asm volatile("cp.async.wait_group 0;\n");
        __syncwarp();

        // compute chunk c: each thread owns one smem row; pack spike bits
        float* rowp = buf + tid * STRIDE;
        unsigned w[WPC] = {0u, 0u, 0u, 0u};
        #pragma unroll
        for (int i = 0; i < CHUNK / 4; ++i) {
            float4 xv = *reinterpret_cast<float4*>(rowp + i * 4);
            #pragma unroll
            for (int k = 0; k < 4; ++k) {
                const float xt = (k == 0) ? xv.x : (k == 1) ? xv.y
                               : (k == 2) ? xv.z : xv.w;
                const float ic = (xt * m2) * m1;          // refractory mask
                const float nm = fmaf(mem, beta_c, ic);   // leaky integrate
                const bool  sp = nm > vth;
                const float sv = sp ? 1.0f : 0.0f;
                mem = sp ? 0.0f : nm;                     // reset-to-zero
                a   = fmaf(p_c, a, sv);                   // adaptation
                vth = fmaf(b_c, a, 1.0f);
                m2 = m1; m1 = sp ? 0.0f : 1.0f;
                const int t = i * 4 + k;                  // step within chunk
                w[t >> 5] |= (sp ? 1u : 0u) << (t & 31);
            }
        }
        #pragma unroll
        for (int j = 0; j < WPC; ++j)
            bits[tid][c * WPC + j] = w[j];
        __syncwarp();

        // prefetch chunk c+2 into the buffer just consumed
        if (c + 2 < NCHUNK) {
            const float* base = x + row_base * T_STEPS + (c + 2) * CHUNK;
            #pragma unroll
            for (int k = 0; k < LDI; ++k)
                cp_async16(buf + k * STRIDE + tid * 4, base + k * T_STEPS + tid * 4);
            asm volatile("cp.async.commit_group;\n");
        }
    }
    __syncwarp();   // all bit-words visible warp-wide

    // ---- output sweep: expand bits -> fp32, one contiguous 64 KB stream ----
    // iteration it: row r = it>>2, 512B segment i = it&3 (segment = chunk c).
    // lane j writes float4 at out[(row_base+r)*512 + i*128 + j*4].
    // bit for element e: word i*4 + (j>>3), bit (j&7)*4 + e.
    float* obase = out + row_base * T_STEPS;
    const unsigned sh = (tid & 7) * 4;
    #pragma unroll 4
    for (int it = 0; it < ROWS * NCHUNK; ++it) {
        const int r = it >> 2, i = it & 3;
        const unsigned word = bits[r][i * 4 + (tid >> 3)];
        float4 v;
        v.x = (word >> (sh + 0)) & 1u ? 1.0f : 0.0f;
        v.y = (word >> (sh + 1)) & 1u ? 1.0f : 0.0f;
        v.z = (word >> (sh + 2)) & 1u ? 1.0f : 0.0f;
        v.w = (word >> (sh + 3)) & 1u ? 1.0f : 0.0f;
        __stcs(reinterpret_cast<float4*>(
            obase + (size_t)r * T_STEPS + i * CHUNK + tid * 4), v);
    }
}

extern "C" void kernel_launch(void* const* d_in, const int* in_sizes, int n_in,
                              void* d_out, int out_size)
{
    const float* x    = (const float*)d_in[0];
    const float* beta = (const float*)d_in[1];
    const float* p    = (const float*)d_in[2];
    const float* b    = (const float*)d_in[3];
    float* out        = (float*)d_out;

    const int N    = in_sizes[1];               // 1024
    const int rows = in_sizes[0] / T_STEPS;     // B*N = 65536

    const int blocks = rows / ROWS;             // 2048
    snn_fwd_kernel<<<blocks, ROWS>>>(x, beta, p, b, out, N);
}

// round 13
// speedup vs baseline: 1.1187x; 1.1187x over previous
#include <cuda_runtime.h>

// SNN forward scan: rows = B*N = 65536 independent length-512 recurrences.
// R13: fine-granule variant of R9. 16 rows per 32-thread block (4096 blocks,
// 16.9 KB smem -> ~13 resident blocks/SM, halved drain-tail granularity).
// CHUNK=128: each cooperative iteration moves one row's full contiguous
// 512 B run with all 32 lanes (one DRAM page burst). Double-buffered
// cp.async, issue-then-wait. Threads 16-31 participate in transfers only.
// Refractory window as multiplicative mask: ic = x*(1-s[t-1])*(1-s[t-2]).

#define T_STEPS 512
#define CHUNK   128
#define RPB     16                 // rows per block
#define THREADS 32                 // one warp
#define NCHUNK  (T_STEPS / CHUNK)  // 4
#define STRIDE  132                // padded smem row stride (floats); conflict-free
#define LDI     RPB                // coop iterations per stage (one 512B row-run each)

__device__ __forceinline__ void cp_async16(float* smem_dst, const float* gmem_src) {
    unsigned saddr = (unsigned)__cvta_generic_to_shared(smem_dst);
    asm volatile("cp.async.cg.shared.global [%0], [%1], 16;\n"
                 :: "r"(saddr), "l"(gmem_src));
}

__global__ __launch_bounds__(THREADS) void snn_fwd_kernel(
    const float* __restrict__ x,
    const float* __restrict__ beta,
    const float* __restrict__ p,
    const float* __restrict__ b,
    float* __restrict__ out,
    int N)
{
    __shared__ float tile[2][RPB * STRIDE];

    const int tid = threadIdx.x;
    const size_t row_base = (size_t)blockIdx.x * RPB;
    const int n = (int)((row_base + (tid & 15)) % (size_t)N);

    // clamped effective per-neuron params (only meaningful for tid < 16)
    const float beta_c = fminf(fmaxf(beta[n], 0.001f), 0.999f);
    const float p_c    = fminf(fabsf(p[n]), 0.999f);
    const float b_c    = fminf(fmaxf(fabsf(b[n]), 0.001f), 1.0f);

    // recurrence state
    float mem = 0.0f, a = 0.0f, vth = 1.0f;
    float m1 = 1.0f, m2 = 1.0f;   // 1 - s(t-1), 1 - s(t-2)

    // ---- preload chunks 0 and 1: iteration k = one 512B run of row k ----
    #pragma unroll
    for (int t = 0; t < 2; ++t) {
        const float* base = x + row_base * T_STEPS + t * CHUNK;
        #pragma unroll
        for (int k = 0; k < LDI; ++k)
            cp_async16(&tile[t][k * STRIDE + tid * 4], base + k * T_STEPS + tid * 4);
        asm volatile("cp.async.commit_group;\n");
    }

    #pragma unroll
    for (int c = 0; c < NCHUNK; ++c) {
        float* buf = tile[c & 1];

        if (c + 1 < NCHUNK) asm volatile("cp.async.wait_group 1;\n");
        else                asm volatile("cp.async.wait_group 0;\n");
        __syncwarp();

        // compute: threads 0..15 each own one smem row; overwrite x w/ spikes
        if (tid < RPB) {
            float* rowp = buf + tid * STRIDE;
            #pragma unroll 8
            for (int i = 0; i < CHUNK / 4; ++i) {
                float4 xv = *reinterpret_cast<float4*>(rowp + i * 4);
                float4 ov;
                #pragma unroll
                for (int k = 0; k < 4; ++k) {
                    const float xt = (k == 0) ? xv.x : (k == 1) ? xv.y
                                   : (k == 2) ? xv.z : xv.w;
                    const float ic = (xt * m2) * m1;          // refractory mask
                    const float nm = fmaf(mem, beta_c, ic);   // leaky integrate
                    const bool  sp = nm > vth;
                    const float sv = sp ? 1.0f : 0.0f;
                    mem = sp ? 0.0f : nm;                     // reset-to-zero
                    a   = fmaf(p_c, a, sv);                   // adaptation
                    vth = fmaf(b_c, a, 1.0f);
                    m2 = m1; m1 = sp ? 0.0f : 1.0f;
                    if (k == 0) ov.x = sv; else if (k == 1) ov.y = sv;
                    else if (k == 2) ov.z = sv; else ov.w = sv;
                }
                *reinterpret_cast<float4*>(rowp + i * 4) = ov;
            }
        }
        __syncwarp();   // spikes visible warp-wide

        // cooperative store: one contiguous 512B run per iteration
        {
            float* obase = out + row_base * T_STEPS + (size_t)c * CHUNK;
            #pragma unroll
            for (int k = 0; k < LDI; ++k) {
                const float4 v = *reinterpret_cast<const float4*>(
                    buf + k * STRIDE + tid * 4);
                __stcs(reinterpret_cast<float4*>(obase + k * T_STEPS + tid * 4), v);
            }
        }

        // prefetch chunk c+2 into the buffer just consumed (program-ordered
        // after the store loop: same thread covers the same smem addresses)
        if (c + 2 < NCHUNK) {
            const float* base = x + row_base * T_STEPS + (c + 2) * CHUNK;
            #pragma unroll
            for (int k = 0; k < LDI; ++k)
                cp_async16(buf + k * STRIDE + tid * 4, base + k * T_STEPS + tid * 4);
            asm volatile("cp.async.commit_group;\n");
        }
    }
}

extern "C" void kernel_launch(void* const* d_in, const int* in_sizes, int n_in,
                              void* d_out, int out_size)
{
    const float* x    = (const float*)d_in[0];
    const float* beta = (const float*)d_in[1];
    const float* p    = (const float*)d_in[2];
    const float* b    = (const float*)d_in[3];
    float* out        = (float*)d_out;

    const int N    = in_sizes[1];               // 1024
    const int rows = in_sizes[0] / T_STEPS;     // B*N = 65536

    const int blocks = rows / RPB;              // 4096
    snn_fwd_kernel<<<blocks, THREADS>>>(x, beta, p, b, out, N);
}